// round 3
// baseline (speedup 1.0000x reference)
#include <cuda_runtime.h>
#include <cuda_bf16.h>
#include <cstdint>

typedef unsigned long long ull;

// ---------------- scratch (device globals: allocation-free) ----------------
__device__ float g_xw[(size_t)64 * 1024 * 1536];   // 402 MB input projections
__device__ float g_h0[64 * 512];
__device__ float g_h1[64 * 512];
__device__ unsigned g_ctr[128 * 32];               // per-producer-CTA counters, 128B apart

// ---------------- f32x2 helpers ----------------
__device__ __forceinline__ void fma2(ull& d, ull a, ull b) {
    asm("fma.rn.f32x2 %0, %1, %2, %0;" : "+l"(d) : "l"(a), "l"(b));
}
__device__ __forceinline__ ull splat2(float x) {
    ull r; asm("mov.b64 %0, {%1, %1};" : "=l"(r) : "f"(x)); return r;
}
__device__ __forceinline__ ull pack2(float x, float y) {
    ull r; asm("mov.b64 %0, {%1, %2};" : "=l"(r) : "f"(x), "f"(y)); return r;
}
__device__ __forceinline__ void f4_to_u2(float4 v, ull& a, ull& b) {
    asm("mov.b64 %0, {%1, %2};" : "=l"(a) : "f"(v.x), "f"(v.y));
    asm("mov.b64 %0, {%1, %2};" : "=l"(b) : "f"(v.z), "f"(v.w));
}
__device__ __forceinline__ float2 unpk(ull v) {
    float2 r; asm("mov.b64 {%0, %1}, %2;" : "=f"(r.x), "=f"(r.y) : "l"(v)); return r;
}

__device__ __forceinline__ float sigf(float x) {
    return __fdividef(1.0f, 1.0f + __expf(-x));
}
__device__ __forceinline__ float tanh_acc(float x) {
    float ax = fabsf(x);
    float e = __expf(-2.0f * ax);
    float r = __fdividef(1.0f - e, 1.0f + e);
    return copysignf(r, x);
}

// ============================================================================
// Phase 1: xw = x @ W + b_in    (M=65536, K=512, N=1536), f32x2 SGEMM
//   128x256 tile, 256 threads, 8m x 16n microtile (4 groups of 4 cols).
// ============================================================================
#define P1_BM 128
#define P1_BN 256
#define P1_BK 16

__global__ void __launch_bounds__(256, 1) gemm_xw_kernel(
    const float* __restrict__ A,     // [65536, 512]
    const float* __restrict__ W,     // [512, 1536]
    const float* __restrict__ bias,  // [2, 1536] (row 0 = b_in)
    float* __restrict__ C)           // [65536, 1536]
{
    __shared__ float As[P1_BK * (P1_BM + 4)];   // transposed: As[k][m]
    __shared__ float Bs[P1_BK * P1_BN];         // Bs[k][n]

    const int tid = threadIdx.x;
    const int tx = tid & 15;          // 16 n-thread-cols (4 floats each, x4 groups)
    const int ty = tid >> 4;          // 16 m-groups (8 rows each)
    const int bm = blockIdx.y * P1_BM;
    const int bn = blockIdx.x * P1_BN;

    ull acc[8][8];
#pragma unroll
    for (int m = 0; m < 8; m++)
#pragma unroll
        for (int g = 0; g < 8; g++) acc[m][g] = 0ull;

    for (int kk = 0; kk < 512; kk += P1_BK) {
        // A tile 128x16 (512 float4 slots, 2 per thread), transpose into As
#pragma unroll
        for (int i = 0; i < 2; i++) {
            int s = tid + i * 256;
            int m = s >> 2;
            int kq = (s & 3) << 2;
            float4 v = *(const float4*)(A + (size_t)(bm + m) * 512 + kk + kq);
            As[(kq + 0) * (P1_BM + 4) + m] = v.x;
            As[(kq + 1) * (P1_BM + 4) + m] = v.y;
            As[(kq + 2) * (P1_BM + 4) + m] = v.z;
            As[(kq + 3) * (P1_BM + 4) + m] = v.w;
        }
        // B tile 16x256 (1024 float4 slots, 4 per thread)
#pragma unroll
        for (int i = 0; i < 4; i++) {
            int s = tid + i * 256;
            int k = s >> 6;
            int n4 = (s & 63) << 2;
            float4 v = *(const float4*)(W + (size_t)(kk + k) * 1536 + bn + n4);
            *(float4*)(Bs + k * P1_BN + n4) = v;
        }
        __syncthreads();

#pragma unroll
        for (int k = 0; k < P1_BK; k++) {
            float4 a0 = *(const float4*)(As + k * (P1_BM + 4) + ty * 8);
            float4 a1 = *(const float4*)(As + k * (P1_BM + 4) + ty * 8 + 4);
            ull bp[8];
#pragma unroll
            for (int g = 0; g < 4; g++) {
                float4 b4 = *(const float4*)(Bs + k * P1_BN + tx * 4 + 64 * g);
                f4_to_u2(b4, bp[2 * g], bp[2 * g + 1]);
            }
            float am[8] = {a0.x, a0.y, a0.z, a0.w, a1.x, a1.y, a1.z, a1.w};
#pragma unroll
            for (int m = 0; m < 8; m++) {
                ull as = splat2(am[m]);
#pragma unroll
                for (int g = 0; g < 8; g++) fma2(acc[m][g], as, bp[g]);
            }
        }
        __syncthreads();
    }

    float4 bi[4];
#pragma unroll
    for (int g = 0; g < 4; g++)
        bi[g] = *(const float4*)(bias + bn + tx * 4 + 64 * g);
#pragma unroll
    for (int m = 0; m < 8; m++) {
        float* crow = C + (size_t)(bm + ty * 8 + m) * 1536;
#pragma unroll
        for (int g = 0; g < 4; g++) {
            float2 p0 = unpk(acc[m][2 * g]);
            float2 p1 = unpk(acc[m][2 * g + 1]);
            float4 o;
            o.x = p0.x + bi[g].x; o.y = p0.y + bi[g].y;
            o.z = p1.x + bi[g].z; o.w = p1.y + bi[g].w;
            *(float4*)(crow + bn + tx * 4 + 64 * g) = o;
        }
    }
}

// ============================================================================
// Phase 2: GRU recurrence, 128 CTAs = 8 batch-groups x 16 unit-groups.
//   CTA = (bg: 8 batches, ug: 32 units). R slice in registers (96 f32x2/thread).
//   Fine-grained sync: per-producer-CTA counters; warp w only polls its own
//   2 producers (ug = 2w, 2w+1) and proceeds independently. Release via
//   red.release.gpu.add (no MEMBAR). h_prev carried in a register.
// ============================================================================
#define NB2 128

__global__ void __launch_bounds__(256, 1) gru_seq_kernel(
    const float* __restrict__ xw,    // [65536, 1536]  (b*1024+t major)
    const float* __restrict__ rk,    // [512, 1536]
    const float* __restrict__ bias,  // [2, 1536] (row 1 = b_rec)
    float* __restrict__ out,         // [64, 1024, 512]
    float* __restrict__ h0buf,
    float* __restrict__ h1buf,
    unsigned* __restrict__ ctr)
{
    __shared__ float hs[8][512];         // warp w's h chunk: [b][j] = hs[w][b*64+j]
    __shared__ float red[256 * 25];      // kc-partials (25 = pad, coprime 32)

    const int tid = threadIdx.x;
    const int bgid = blockIdx.x >> 4;    // 0..7
    const int ugid = blockIdx.x & 15;    // 0..15
    const int u0 = ugid * 32;
    const int b0 = bgid * 8;

    const int w  = tid >> 5;             // warp: GEMM k-chunk / epilogue batch
    const int uu = tid & 31;             // lane: unit within group

    // ---- load R slice into registers: unit u0+uu, k in [w*64, w*64+64) ----
    ull Rz[32], Rr[32], Rh[32];
    {
        const float* rbase = rk + u0 + uu;
#pragma unroll
        for (int i = 0; i < 32; i++) {
            int k = w * 64 + 2 * i;
            const float* r0 = rbase + (size_t)k * 1536;
            const float* r1 = r0 + 1536;
            Rz[i] = pack2(r0[0],    r1[0]);
            Rr[i] = pack2(r0[512],  r1[512]);
            Rh[i] = pack2(r0[1024], r1[1024]);
        }
    }
    const float bz  = bias[1536 + u0 + uu];
    const float brr = bias[1536 + 512 + u0 + uu];
    const float bh  = bias[1536 + 1024 + u0 + uu];

    const int bglob = b0 + w;                                 // epilogue batch
    const float* xwp = xw + (size_t)bglob * 1024 * 1536 + u0 + uu;
    float* outp = out + (size_t)bglob * 524288 + u0 + uu;

    unsigned* myctr = ctr + blockIdx.x * 32;                   // own counter
    // warp w consumes producers ug=2w (lane 0) and ug=2w+1 (lane 1)
    unsigned* pollctr = ctr + (bgid * 16 + 2 * w + (uu & 1)) * 32;

    float hn_prev = 0.0f;   // h[bglob][u0+uu] from previous step (h0 = 0)

    for (int t = 0; t < 1024; t++) {
        const float* hin  = (t & 1) ? h1buf : h0buf;
        float*       hout = (t & 1) ? h0buf : h1buf;

        // prefetch gate inputs for this step (independent of h)
        const float* xr_ = xwp + (size_t)t * 1536;
        float xz = __ldg(xr_);
        float xr = __ldg(xr_ + 512);
        float xh = __ldg(xr_ + 1024);

        // ---- wait for THIS warp's 2 producers only ----
        if (t > 0) {
            if (uu < 2) {
                unsigned v;
                do {
                    asm volatile("ld.acquire.gpu.global.u32 %0, [%1];"
                                 : "=r"(v) : "l"(pollctr) : "memory");
                } while (v < (unsigned)t);
            }
            __syncwarp();
        }

        // ---- stage this warp's h chunk: 2 KB, 4 float4 per lane ----
#pragma unroll
        for (int i = 0; i < 4; i++) {
            int s = i * 32 + uu;              // float4 slot in warp region
            int b = s >> 4;
            int j4 = s & 15;
            float4 v = __ldcg((const float4*)(hin + (b0 + b) * 512 + w * 64) + j4);
            *(float4*)(&hs[w][b * 64 + j4 * 4]) = v;
        }
        __syncwarp();

        // ---- GEMM partials: warp w, k-chunk [w*64, w*64+64) ----
#pragma unroll 1
        for (int b = 0; b < 8; b++) {
            ull az = 0ull, ar = 0ull, ah = 0ull;
            const float4* hp = (const float4*)(&hs[w][b * 64]);
#pragma unroll
            for (int q = 0; q < 16; q++) {
                float4 h4 = hp[q];                 // broadcast across warp
                ull h01, h23;
                f4_to_u2(h4, h01, h23);
                fma2(az, h01, Rz[2 * q]); fma2(az, h23, Rz[2 * q + 1]);
                fma2(ar, h01, Rr[2 * q]); fma2(ar, h23, Rr[2 * q + 1]);
                fma2(ah, h01, Rh[2 * q]); fma2(ah, h23, Rh[2 * q + 1]);
            }
            float2 pz = unpk(az), pr = unpk(ar), ph = unpk(ah);
            float* rb = red + (b * 32 + uu) * 25 + w * 3;
            rb[0] = pz.x + pz.y;
            rb[1] = pr.x + pr.y;
            rb[2] = ph.x + ph.y;
        }
        __syncthreads();

        // ---- gates: thread = (batch w, unit uu) ----
        float rz = bz, rr = brr, rh = bh;
        const float* rb = red + (w * 32 + uu) * 25;
#pragma unroll
        for (int s = 0; s < 8; s++) {
            rz += rb[s * 3 + 0];
            rr += rb[s * 3 + 1];
            rh += rb[s * 3 + 2];
        }
        float z  = sigf(xz + rz);
        float r  = sigf(xr + rr);
        float hh = tanh_acc(xh + r * rh);
        float hn = z * hn_prev + (1.0f - z) * hh;
        hn_prev = hn;

        __stcg(hout + bglob * 512 + u0 + uu, hn);
        __syncthreads();
        if (tid == 0) {
            // release: all this CTA's hn stores precede this in program order;
            // consumers pair with ld.acquire.gpu on the same counter.
            asm volatile("red.release.gpu.global.add.u32 [%0], %1;"
                         :: "l"(myctr), "r"(1u) : "memory");
        }

        // out write off the critical path (consumers already released)
        outp[(size_t)t * 512] = hn;
    }
}

// ============================================================================
extern "C" void kernel_launch(void* const* d_in, const int* in_sizes, int n_in,
                              void* d_out, int out_size) {
    const float* x    = (const float*)d_in[0];   // [64,1024,512]
    const float* W    = (const float*)d_in[1];   // [512,1536]
    const float* R    = (const float*)d_in[2];   // [512,1536]
    const float* bias = (const float*)d_in[3];   // [2,1536]
    float* out = (float*)d_out;

    float *xw_ptr, *h0_ptr, *h1_ptr;
    unsigned* ctr_ptr;
    cudaGetSymbolAddress((void**)&xw_ptr, g_xw);
    cudaGetSymbolAddress((void**)&h0_ptr, g_h0);
    cudaGetSymbolAddress((void**)&h1_ptr, g_h1);
    cudaGetSymbolAddress((void**)&ctr_ptr, g_ctr);

    cudaMemsetAsync(h0_ptr, 0, 64 * 512 * sizeof(float));
    cudaMemsetAsync(ctr_ptr, 0, 128 * 32 * sizeof(unsigned));

    dim3 g1(1536 / P1_BN, 65536 / P1_BM);
    gemm_xw_kernel<<<g1, 256>>>(x, W, bias, xw_ptr);

    gru_seq_kernel<<<NB2, 256>>>(xw_ptr, R, bias, out, h0_ptr, h1_ptr, ctr_ptr);
}

// round 4
// speedup vs baseline: 1.3556x; 1.3556x over previous
#include <cuda_runtime.h>
#include <cuda_bf16.h>
#include <cstdint>

typedef unsigned long long ull;

// ---------------- scratch (device globals: allocation-free) ----------------
__device__ float g_xw[(size_t)64 * 1024 * 1536];   // 402 MB input projections
__device__ float g_h0[64 * 512];
__device__ float g_h1[64 * 512];
__device__ unsigned g_ctr[8 * 32];                 // fallback: per-bg counters, 128B apart

// ---------------- f32x2 helpers ----------------
__device__ __forceinline__ void fma2(ull& d, ull a, ull b) {
    asm("fma.rn.f32x2 %0, %1, %2, %0;" : "+l"(d) : "l"(a), "l"(b));
}
__device__ __forceinline__ ull splat2(float x) {
    ull r; asm("mov.b64 %0, {%1, %1};" : "=l"(r) : "f"(x)); return r;
}
__device__ __forceinline__ ull pack2(float x, float y) {
    ull r; asm("mov.b64 %0, {%1, %2};" : "=l"(r) : "f"(x), "f"(y)); return r;
}
__device__ __forceinline__ void f4_to_u2(float4 v, ull& a, ull& b) {
    asm("mov.b64 %0, {%1, %2};" : "=l"(a) : "f"(v.x), "f"(v.y));
    asm("mov.b64 %0, {%1, %2};" : "=l"(b) : "f"(v.z), "f"(v.w));
}
__device__ __forceinline__ float2 unpk(ull v) {
    float2 r; asm("mov.b64 {%0, %1}, %2;" : "=f"(r.x), "=f"(r.y) : "l"(v)); return r;
}
__device__ __forceinline__ uint32_t smem_u32(const void* p) {
    uint32_t a;
    asm("{ .reg .u64 t; cvta.to.shared.u64 t, %1; cvt.u32.u64 %0, t; }" : "=r"(a) : "l"(p));
    return a;
}

__device__ __forceinline__ float sigf(float x) {
    return __fdividef(1.0f, 1.0f + __expf(-x));
}
__device__ __forceinline__ float tanh_acc(float x) {
    float ax = fabsf(x);
    float e = __expf(-2.0f * ax);
    float r = __fdividef(1.0f - e, 1.0f + e);
    return copysignf(r, x);
}

// ============================================================================
// Phase 1: xw = x @ W + b_in    (M=65536, K=512, N=1536), f32x2 SGEMM
//   128x256 tile, 256 threads, 8m x 16n microtile (4 groups of 4 cols).
// ============================================================================
#define P1_BM 128
#define P1_BN 256
#define P1_BK 16

__global__ void __launch_bounds__(256, 1) gemm_xw_kernel(
    const float* __restrict__ A,     // [65536, 512]
    const float* __restrict__ W,     // [512, 1536]
    const float* __restrict__ bias,  // [2, 1536] (row 0 = b_in)
    float* __restrict__ C)           // [65536, 1536]
{
    __shared__ float As[P1_BK * (P1_BM + 4)];   // transposed: As[k][m]
    __shared__ float Bs[P1_BK * P1_BN];         // Bs[k][n]

    const int tid = threadIdx.x;
    const int tx = tid & 15;
    const int ty = tid >> 4;
    const int bm = blockIdx.y * P1_BM;
    const int bn = blockIdx.x * P1_BN;

    ull acc[8][8];
#pragma unroll
    for (int m = 0; m < 8; m++)
#pragma unroll
        for (int g = 0; g < 8; g++) acc[m][g] = 0ull;

    for (int kk = 0; kk < 512; kk += P1_BK) {
#pragma unroll
        for (int i = 0; i < 2; i++) {
            int s = tid + i * 256;
            int m = s >> 2;
            int kq = (s & 3) << 2;
            float4 v = *(const float4*)(A + (size_t)(bm + m) * 512 + kk + kq);
            As[(kq + 0) * (P1_BM + 4) + m] = v.x;
            As[(kq + 1) * (P1_BM + 4) + m] = v.y;
            As[(kq + 2) * (P1_BM + 4) + m] = v.z;
            As[(kq + 3) * (P1_BM + 4) + m] = v.w;
        }
#pragma unroll
        for (int i = 0; i < 4; i++) {
            int s = tid + i * 256;
            int k = s >> 6;
            int n4 = (s & 63) << 2;
            float4 v = *(const float4*)(W + (size_t)(kk + k) * 1536 + bn + n4);
            *(float4*)(Bs + k * P1_BN + n4) = v;
        }
        __syncthreads();

#pragma unroll
        for (int k = 0; k < P1_BK; k++) {
            float4 a0 = *(const float4*)(As + k * (P1_BM + 4) + ty * 8);
            float4 a1 = *(const float4*)(As + k * (P1_BM + 4) + ty * 8 + 4);
            ull bp[8];
#pragma unroll
            for (int g = 0; g < 4; g++) {
                float4 b4 = *(const float4*)(Bs + k * P1_BN + tx * 4 + 64 * g);
                f4_to_u2(b4, bp[2 * g], bp[2 * g + 1]);
            }
            float am[8] = {a0.x, a0.y, a0.z, a0.w, a1.x, a1.y, a1.z, a1.w};
#pragma unroll
            for (int m = 0; m < 8; m++) {
                ull as = splat2(am[m]);
#pragma unroll
                for (int g = 0; g < 8; g++) fma2(acc[m][g], as, bp[g]);
            }
        }
        __syncthreads();
    }

    float4 bi[4];
#pragma unroll
    for (int g = 0; g < 4; g++)
        bi[g] = *(const float4*)(bias + bn + tx * 4 + 64 * g);
#pragma unroll
    for (int m = 0; m < 8; m++) {
        float* crow = C + (size_t)(bm + ty * 8 + m) * 1536;
#pragma unroll
        for (int g = 0; g < 4; g++) {
            float2 p0 = unpk(acc[m][2 * g]);
            float2 p1 = unpk(acc[m][2 * g + 1]);
            float4 o;
            o.x = p0.x + bi[g].x; o.y = p0.y + bi[g].y;
            o.z = p1.x + bi[g].z; o.w = p1.y + bi[g].w;
            *(float4*)(crow + bn + tx * 4 + 64 * g) = o;
        }
    }
}

// ============================================================================
// Phase 2: GRU recurrence, 128 CTAs = 8 batch-groups x 16 unit-groups.
//   Cluster mode (use_cluster=1): cluster = 16 CTAs of one batch-group;
//   per-CTA smem mbarrier (count 16); producers remote-arrive on all 16 peers
//   (release.cluster); consumer does one try_wait (acquire.cluster).
//   Fallback (use_cluster=0): R2's fence + atomicAdd + acquire-poll counter.
//   R slice in registers (96 f32x2/thread). h exchanged via global (L2, .cg).
// ============================================================================
#define NB2 128

__global__ void __launch_bounds__(256, 1) gru_seq_kernel(
    const float* __restrict__ xw,    // [65536, 1536]  (b*1024+t major)
    const float* __restrict__ rk,    // [512, 1536]
    const float* __restrict__ bias,  // [2, 1536] (row 1 = b_rec)
    float* __restrict__ out,         // [64, 1024, 512]
    float* __restrict__ h0buf,
    float* __restrict__ h1buf,
    unsigned* __restrict__ ctr,
    int use_cluster)
{
    __shared__ float hs[8 * 512];        // h staging: [b*512 + k]
    __shared__ float red[256 * 25];      // kc-partials (25 = pad, coprime 32)
    __shared__ ull mbar;

    const int tid = threadIdx.x;
    const int bgid = blockIdx.x >> 4;    // 0..7  (== cluster id in cluster mode)
    const int ugid = blockIdx.x & 15;    // 0..15 (== cluster rank)
    const int u0 = ugid * 32;
    const int b0 = bgid * 8;

    const int w  = tid >> 5;             // warp: GEMM k-chunk / epilogue batch
    const int uu = tid & 31;             // lane: unit within group

    const uint32_t mb = smem_u32(&mbar);
    if (use_cluster) {
        if (tid == 0) {
            asm volatile("mbarrier.init.shared.b64 [%0], 16;" :: "r"(mb) : "memory");
        }
        __syncthreads();
        asm volatile("barrier.cluster.arrive.aligned;" ::: "memory");
        asm volatile("barrier.cluster.wait.aligned;" ::: "memory");
    }

    // ---- load R slice into registers: unit u0+uu, k in [w*64, w*64+64) ----
    ull Rz[32], Rr[32], Rh[32];
    {
        const float* rbase = rk + u0 + uu;
#pragma unroll
        for (int i = 0; i < 32; i++) {
            int k = w * 64 + 2 * i;
            const float* r0 = rbase + (size_t)k * 1536;
            const float* r1 = r0 + 1536;
            Rz[i] = pack2(r0[0],    r1[0]);
            Rr[i] = pack2(r0[512],  r1[512]);
            Rh[i] = pack2(r0[1024], r1[1024]);
        }
    }
    const float bz  = bias[1536 + u0 + uu];
    const float brr = bias[1536 + 512 + u0 + uu];
    const float bh  = bias[1536 + 1024 + u0 + uu];

    const int bglob = b0 + w;                                 // epilogue batch
    const float* xwp = xw + (size_t)bglob * 1024 * 1536 + u0 + uu;
    float* outp = out + (size_t)bglob * 524288 + u0 + uu;
    unsigned* myctr = ctr + bgid * 32;

    float hn_prev = 0.0f;   // h[bglob][u0+uu] from previous step (h0 = 0)

    for (int t = 0; t < 1024; t++) {
        const float* hin  = (t & 1) ? h1buf : h0buf;
        float*       hout = (t & 1) ? h0buf : h1buf;

        // prefetch gate inputs for this step (independent of h)
        const float* xr_ = xwp + (size_t)t * 1536;
        float xz = __ldg(xr_);
        float xr = __ldg(xr_ + 512);
        float xh = __ldg(xr_ + 1024);

        // ---- wait for h_t from the 16 CTAs of this batch-group ----
        if (t > 0) {
            if (tid == 0) {
                if (use_cluster) {
                    unsigned parity = (unsigned)((t - 1) & 1);
                    uint32_t done;
                    do {
                        asm volatile(
                            "{\n\t.reg .pred p;\n\t"
                            "mbarrier.try_wait.parity.acquire.cluster.shared::cta.b64 p, [%1], %2, 0x989680;\n\t"
                            "selp.b32 %0, 1, 0, p;\n\t}"
                            : "=r"(done) : "r"(mb), "r"(parity) : "memory");
                    } while (!done);
                } else {
                    unsigned target = (unsigned)(16 * t);
                    unsigned v;
                    do {
                        asm volatile("ld.acquire.gpu.global.u32 %0, [%1];"
                                     : "=r"(v) : "l"(myctr) : "memory");
                    } while (v < target);
                }
            }
            __syncthreads();
        }

        // ---- per-warp staging: warp w stages k in [64w,64w+64) for all 8 b ----
#pragma unroll
        for (int i = 0; i < 4; i++) {
            int s = i * 32 + uu;          // 0..127
            int b = s >> 4;
            int j4 = s & 15;
            float4 v = __ldcg((const float4*)(hin + (b0 + b) * 512 + w * 64) + j4);
            *(float4*)(hs + b * 512 + w * 64 + j4 * 4) = v;
        }
        __syncwarp();

        // ---- GEMM partials: warp w, k-chunk [w*64, w*64+64) ----
#pragma unroll 1
        for (int b = 0; b < 8; b++) {
            ull az = 0ull, ar = 0ull, ah = 0ull;
            const float4* hp = (const float4*)(hs + b * 512 + w * 64);
#pragma unroll
            for (int q = 0; q < 16; q++) {
                float4 h4 = hp[q];                 // broadcast across warp
                ull h01, h23;
                f4_to_u2(h4, h01, h23);
                fma2(az, h01, Rz[2 * q]); fma2(az, h23, Rz[2 * q + 1]);
                fma2(ar, h01, Rr[2 * q]); fma2(ar, h23, Rr[2 * q + 1]);
                fma2(ah, h01, Rh[2 * q]); fma2(ah, h23, Rh[2 * q + 1]);
            }
            float2 pz = unpk(az), pr = unpk(ar), ph = unpk(ah);
            float* rb = red + (b * 32 + uu) * 25 + w * 3;
            rb[0] = pz.x + pz.y;
            rb[1] = pr.x + pr.y;
            rb[2] = ph.x + ph.y;
        }
        __syncthreads();

        // ---- gates: thread = (batch w, unit uu) ----
        float rz = bz, rr = brr, rh = bh;
        const float* rb = red + (w * 32 + uu) * 25;
#pragma unroll
        for (int s = 0; s < 8; s++) {
            rz += rb[s * 3 + 0];
            rr += rb[s * 3 + 1];
            rh += rb[s * 3 + 2];
        }
        float z  = sigf(xz + rz);
        float r  = sigf(xr + rr);
        float hh = tanh_acc(xh + r * rh);
        float hn = z * hn_prev + (1.0f - z) * hh;
        hn_prev = hn;

        __stcg(hout + bglob * 512 + u0 + uu, hn);
        if (!use_cluster) __threadfence();
        __syncthreads();
        if (tid == 0) {
            if (use_cluster) {
                // release-arrive on every cluster CTA's mbarrier (incl. self)
#pragma unroll 4
                for (int rnk = 0; rnk < 16; rnk++) {
                    asm volatile(
                        "{\n\t.reg .b32 ra;\n\t"
                        "mapa.shared::cluster.u32 ra, %0, %1;\n\t"
                        "mbarrier.arrive.release.cluster.shared::cluster.b64 _, [ra];\n\t}"
                        :: "r"(mb), "r"(rnk) : "memory");
                }
            } else {
                atomicAdd(myctr, 1u);
            }
        }

        // out write off the critical path (consumers already released)
        outp[(size_t)t * 512] = hn;
    }
}

// ============================================================================
extern "C" void kernel_launch(void* const* d_in, const int* in_sizes, int n_in,
                              void* d_out, int out_size) {
    const float* x    = (const float*)d_in[0];   // [64,1024,512]
    const float* W    = (const float*)d_in[1];   // [512,1536]
    const float* R    = (const float*)d_in[2];   // [512,1536]
    const float* bias = (const float*)d_in[3];   // [2,1536]
    float* out = (float*)d_out;

    float *xw_ptr, *h0_ptr, *h1_ptr;
    unsigned* ctr_ptr;
    cudaGetSymbolAddress((void**)&xw_ptr, g_xw);
    cudaGetSymbolAddress((void**)&h0_ptr, g_h0);
    cudaGetSymbolAddress((void**)&h1_ptr, g_h1);
    cudaGetSymbolAddress((void**)&ctr_ptr, g_ctr);

    cudaMemsetAsync(h0_ptr, 0, 64 * 512 * sizeof(float));
    cudaMemsetAsync(ctr_ptr, 0, 8 * 32 * sizeof(unsigned));

    dim3 g1(1536 / P1_BN, 65536 / P1_BM);
    gemm_xw_kernel<<<g1, 256>>>(x, W, bias, xw_ptr);

    // ---- phase 2: try 16-CTA clusters, fall back to counter sync ----
    cudaFuncSetAttribute(gru_seq_kernel,
                         cudaFuncAttributeNonPortableClusterSizeAllowed, 1);

    cudaLaunchConfig_t cfg = {};
    cfg.gridDim = dim3(NB2, 1, 1);
    cfg.blockDim = dim3(256, 1, 1);
    cfg.dynamicSmemBytes = 0;
    cudaLaunchAttribute attrs[1];
    attrs[0].id = cudaLaunchAttributeClusterDimension;
    attrs[0].val.clusterDim = {16, 1, 1};
    cfg.attrs = attrs;
    cfg.numAttrs = 1;

    int nclusters = 0;
    cudaError_t qe = cudaOccupancyMaxActiveClusters(&nclusters, gru_seq_kernel, &cfg);
    int use_cluster = (qe == cudaSuccess && nclusters >= 8) ? 1 : 0;
    if (!use_cluster) (void)cudaGetLastError();   // clear sticky query error

    if (use_cluster) {
        cudaError_t le = cudaLaunchKernelEx(&cfg, gru_seq_kernel,
                                            (const float*)xw_ptr, R, bias, out,
                                            h0_ptr, h1_ptr, ctr_ptr, 1);
        if (le != cudaSuccess) {
            (void)cudaGetLastError();
            use_cluster = 0;
        }
    }
    if (!use_cluster) {
        gru_seq_kernel<<<NB2, 256>>>(xw_ptr, R, bias, out,
                                     h0_ptr, h1_ptr, ctr_ptr, 0);
    }
}